// round 13
// baseline (speedup 1.0000x reference)
#include <cuda_runtime.h>
#include <cuda_bf16.h>
#include <cstdint>
#include <cstddef>

#define NNODE 50000
#define IN_DIM 32
#define HID 128
#define OUT_DIMS 10
#define KCH 5
#define EPK 400000
#define NEDGE (KCH * EPK)
#define NGROUP 500
#define SCAN_BLOCKS 25   // ceil(50000/2048)

// ---------------- scratch (device globals; no allocations allowed) ----------
__device__ float g_h1m[2][KCH][(size_t)NNODE * HID]; // per-k GEMM outputs, dbl-buffered by layer parity
__device__ float g_x5[(size_t)NNODE * HID];          // final activations (pool input)
__device__ uint32_t g_hbh[6][(size_t)NNODE * 64];    // x_l bf16-hi (bf16x2 words)
__device__ uint32_t g_hbl[6][(size_t)NNODE * 64];    // x_l bf16-lo
__device__ uint32_t g_xbh[(size_t)NNODE * 16];       // x bf16-hi (K=32)
__device__ uint32_t g_xbl[(size_t)NNODE * 16];
__device__ uint32_t g_wembh[128 * 16];               // emb_W bf16 hi/lo
__device__ uint32_t g_wembl[128 * 16];
__device__ uint32_t g_wconvh[15 * 128 * 64];         // conv_W bf16 hi/lo
__device__ uint32_t g_wconvl[15 * 128 * 64];
__device__ float g_dinv[KCH * NNODE];
__device__ int   g_cnt[KCH * NNODE];
__device__ int   g_rowptr[KCH * (NNODE + 1)];
__device__ int   g_cursor[KCH * NNODE];
__device__ int   g_bsum[KCH * SCAN_BLOCKS];
__device__ int   g_esrc[NEDGE];
__device__ float g_pooled[NGROUP * 3 * HID];

// ---------------- host-side streams/events (static init, pre-checkpoint) ----
struct OverlapCtx {
    cudaStream_t s1 = nullptr;
    cudaEvent_t eFork = nullptr, eCsr = nullptr, eEmb = nullptr;
    cudaEvent_t eA[4] = {};      // agg 0..3
    cudaEvent_t eOld[5] = {};    // old-GEMM batches 1..4
    bool ok = false;
    OverlapCtx() {
        bool good = cudaStreamCreateWithFlags(&s1, cudaStreamNonBlocking) == cudaSuccess;
        auto mk = [&](cudaEvent_t& e) {
            if (good) good = cudaEventCreateWithFlags(&e, cudaEventDisableTiming) == cudaSuccess;
        };
        mk(eFork); mk(eCsr); mk(eEmb);
        for (int i = 0; i < 4; i++) mk(eA[i]);
        for (int i = 1; i < 5; i++) mk(eOld[i]);
        ok = good;
    }
};
static OverlapCtx g_ov;

// ---------------- bf16 split helpers ----------------------------------------
__device__ __forceinline__ void split_pair(float x, float y, uint32_t& h, uint32_t& l) {
    __nv_bfloat162 hb = __floats2bfloat162_rn(x, y);
    float hx = __bfloat162float(hb.x), hy = __bfloat162float(hb.y);
    __nv_bfloat162 lb = __floats2bfloat162_rn(x - hx, y - hy);
    h = *reinterpret_cast<uint32_t*>(&hb);
    l = *reinterpret_cast<uint32_t*>(&lb);
}

__global__ void prep_pairs(const float* __restrict__ src, uint32_t* __restrict__ dh,
                           uint32_t* __restrict__ dl, int npairs) {
    int i = blockIdx.x * blockDim.x + threadIdx.x;
    if (i >= npairs) return;
    float2 v = *reinterpret_cast<const float2*>(src + (size_t)i * 2);
    uint32_t h, l;
    split_pair(v.x, v.y, h, l);
    dh[i] = h;
    dl[i] = l;
}

// ---------------- CSR build -------------------------------------------------
__global__ void count_kernel(const int* __restrict__ kei) {
    int e = blockIdx.x * blockDim.x + threadIdx.x;
    if (e >= NEDGE) return;
    int chunk = e / EPK;
    int d = kei[NEDGE + e];
    atomicAdd(&g_cnt[chunk * NNODE + d], 1);
}

// scan1 also computes dinv (reads the same counts)
__global__ void scan1_kernel() {
    int ch = blockIdx.y, bx = blockIdx.x, tid = threadIdx.x;
    const int* cnt = g_cnt + ch * NNODE;
    int base = bx * 2048 + tid * 8;
    int tot = 0;
#pragma unroll
    for (int i = 0; i < 8; i++) {
        int idx = base + i;
        if (idx < NNODE) {
            int c = cnt[idx];
            tot += c;
            g_dinv[ch * NNODE + idx] = rsqrtf((float)c + 1.0f);
        }
    }
    __shared__ int s[256];
    s[tid] = tot; __syncthreads();
    for (int off = 128; off > 0; off >>= 1) {
        if (tid < off) s[tid] += s[tid + off];
        __syncthreads();
    }
    if (tid == 0) g_bsum[ch * SCAN_BLOCKS + bx] = s[0];
}

__global__ void scan2_kernel() {
    int c = threadIdx.x;
    if (c >= KCH) return;
    int run = 0;
    for (int b = 0; b < SCAN_BLOCKS; b++) {
        int t = g_bsum[c * SCAN_BLOCKS + b];
        g_bsum[c * SCAN_BLOCKS + b] = run;
        run += t;
    }
    g_rowptr[c * (NNODE + 1) + NNODE] = run;
}

__global__ void scan3_kernel() {
    int ch = blockIdx.y, bx = blockIdx.x, tid = threadIdx.x;
    const int* cnt = g_cnt + ch * NNODE;
    int base = bx * 2048 + tid * 8;
    int v[8]; int tot = 0;
#pragma unroll
    for (int i = 0; i < 8; i++) {
        int idx = base + i;
        v[i] = (idx < NNODE) ? cnt[idx] : 0;
        tot += v[i];
    }
    __shared__ int s[256];
    s[tid] = tot; __syncthreads();
    for (int off = 1; off < 256; off <<= 1) {
        int t = (tid >= off) ? s[tid - off] : 0;
        __syncthreads();
        s[tid] += t;
        __syncthreads();
    }
    int excl = s[tid] - tot + g_bsum[ch * SCAN_BLOCKS + bx];
    int* rowp = g_rowptr + ch * (NNODE + 1);
    int* curs = g_cursor + ch * NNODE;
#pragma unroll
    for (int i = 0; i < 8; i++) {
        int idx = base + i;
        if (idx < NNODE) { rowp[idx] = excl; curs[idx] = excl; }
        excl += v[i];
    }
}

__global__ void scatter_kernel(const int* __restrict__ kei) {
    int e = blockIdx.x * blockDim.x + threadIdx.x;
    if (e >= NEDGE) return;
    int chunk = e / EPK;
    int s = kei[e];
    int d = kei[NEDGE + e];
    int pos = atomicAdd(&g_cursor[chunk * NNODE + d], 1);
    g_esrc[(size_t)chunk * EPK + pos] = s;
}

// ---------------- split-bf16 mma.sync GEMM core ------------------------------
__device__ __forceinline__ void mma_bf16(float* c, const uint32_t* a,
                                         uint32_t b0, uint32_t b1) {
    asm volatile(
        "mma.sync.aligned.m16n8k16.row.col.f32.bf16.bf16.f32 "
        "{%0,%1,%2,%3}, {%4,%5,%6,%7}, {%8,%9}, {%0,%1,%2,%3};"
        : "+f"(c[0]), "+f"(c[1]), "+f"(c[2]), "+f"(c[3])
        : "r"(a[0]), "r"(a[1]), "r"(a[2]), "r"(a[3]), "r"(b0), "r"(b1));
}

template <int K>
__device__ __forceinline__ void gemm_body(
    const uint32_t* __restrict__ Ah, const uint32_t* __restrict__ Al,
    const uint32_t* __restrict__ Wh, const uint32_t* __restrict__ Wl,
    const float* __restrict__ bias, float* __restrict__ C,
    uint32_t* __restrict__ Ch, uint32_t* __restrict__ Cl, int M, int m0,
    uint32_t* sm) {
    constexpr int RW = K / 2;
    constexpr int NQ = RW / 4;
    constexpr int QM = (NQ >= 8) ? 7 : (NQ - 1);
    constexpr int NKC = K / 16;

    uint32_t* sWh = sm;
    uint32_t* sWl = sWh + 128 * RW;
    uint32_t* sAh = sWl + 128 * RW;
    uint32_t* sAl = sAh + 64 * RW;

    int tid = threadIdx.x;
    int lane = tid & 31, warp = tid >> 5;
    int wm = warp >> 1, wn = warp & 1;

    for (int idx = tid; idx < 128 * NQ; idx += 256) {
        int r = idx / NQ, q = idx % NQ;
        int dq = q ^ (r & QM);
        *reinterpret_cast<uint4*>(sWh + r * RW + dq * 4) =
            *reinterpret_cast<const uint4*>(Wh + (size_t)r * RW + q * 4);
        *reinterpret_cast<uint4*>(sWl + r * RW + dq * 4) =
            *reinterpret_cast<const uint4*>(Wl + (size_t)r * RW + q * 4);
    }
    for (int idx = tid; idx < 64 * NQ; idx += 256) {
        int r = idx / NQ, q = idx % NQ;
        int row = m0 + r; if (row >= M) row = M - 1;
        int dq = q ^ (r & QM);
        *reinterpret_cast<uint4*>(sAh + r * RW + dq * 4) =
            *reinterpret_cast<const uint4*>(Ah + (size_t)row * RW + q * 4);
        *reinterpret_cast<uint4*>(sAl + r * RW + dq * 4) =
            *reinterpret_cast<const uint4*>(Al + (size_t)row * RW + q * 4);
    }
    __syncthreads();

    float c[8][4];
#pragma unroll
    for (int i = 0; i < 8; i++)
#pragma unroll
        for (int j = 0; j < 4; j++) c[i][j] = 0.f;

    int g = lane >> 2, t = lane & 3;

#define LDW(base, r, w) (base)[(r) * RW + (((((w) >> 2) ^ ((r) & QM))) << 2) + ((w) & 3)]

#pragma unroll
    for (int kc = 0; kc < NKC; kc++) {
        int w0 = kc * 8 + t;
        int w1 = kc * 8 + 4 + t;
        int ra = wm * 16 + g;
        uint32_t ah[4], al[4];
        ah[0] = LDW(sAh, ra, w0);     al[0] = LDW(sAl, ra, w0);
        ah[1] = LDW(sAh, ra + 8, w0); al[1] = LDW(sAl, ra + 8, w0);
        ah[2] = LDW(sAh, ra, w1);     al[2] = LDW(sAl, ra, w1);
        ah[3] = LDW(sAh, ra + 8, w1); al[3] = LDW(sAl, ra + 8, w1);
#pragma unroll
        for (int nt = 0; nt < 8; nt++) {
            int n = wn * 64 + nt * 8 + g;
            uint32_t bh0 = LDW(sWh, n, w0), bh1 = LDW(sWh, n, w1);
            uint32_t bl0 = LDW(sWl, n, w0), bl1 = LDW(sWl, n, w1);
            mma_bf16(c[nt], ah, bh0, bh1);
            mma_bf16(c[nt], al, bh0, bh1);
            mma_bf16(c[nt], ah, bl0, bl1);
        }
    }
#undef LDW

    int r0 = m0 + wm * 16 + g;
    int r1 = r0 + 8;
#pragma unroll
    for (int nt = 0; nt < 8; nt++) {
        int col = wn * 64 + nt * 8 + t * 2;
        float bx = 0.f, by = 0.f;
        if (bias) { bx = bias[col]; by = bias[col + 1]; }
        if (r0 < M) {
            float2 o = make_float2(c[nt][0] + bx, c[nt][1] + by);
            if (C) *reinterpret_cast<float2*>(C + (size_t)r0 * HID + col) = o;
            if (Ch) {
                uint32_t h, l;
                split_pair(o.x, o.y, h, l);
                Ch[(size_t)r0 * 64 + (col >> 1)] = h;
                Cl[(size_t)r0 * 64 + (col >> 1)] = l;
            }
        }
        if (r1 < M) {
            float2 o = make_float2(c[nt][2] + bx, c[nt][3] + by);
            if (C) *reinterpret_cast<float2*>(C + (size_t)r1 * HID + col) = o;
            if (Ch) {
                uint32_t h, l;
                split_pair(o.x, o.y, h, l);
                Ch[(size_t)r1 * 64 + (col >> 1)] = h;
                Cl[(size_t)r1 * 64 + (col >> 1)] = l;
            }
        }
    }
}

// embedding GEMM (K=32): bf16 output only
__global__ __launch_bounds__(256) void gemm_emb(const float* __restrict__ emb_b) {
    extern __shared__ uint32_t sm[];
    gemm_body<IN_DIM>(g_xbh, g_xbl, g_wembh, g_wembl, emb_b,
                      nullptr, g_hbh[0], g_hbl[0], NNODE, blockIdx.x * 64, sm);
}

// conv GEMMs for layer l: y = y0 + blockIdx.y; A = x_l[l-y], C = h1m[buf][y]
__global__ __launch_bounds__(256) void gemm_layer(int l, int ci0, int y0, int buf) {
    extern __shared__ uint32_t sm[];
    int y = y0 + blockIdx.y;
    gemm_body<HID>(g_hbh[l - y], g_hbl[l - y],
                   g_wconvh + (size_t)(ci0 + y) * 128 * 64,
                   g_wconvl + (size_t)(ci0 + y) * 128 * 64,
                   nullptr, g_h1m[buf][y], nullptr, nullptr, NNODE, blockIdx.x * 64, sm);
}

// ---------------- fused per-layer GCN aggregation ----------------------------
__global__ __launch_bounds__(256) void agg_layer(
    int l, int ci0, const float* __restrict__ conv_b, int write_float, int buf) {
    int w = (blockIdx.x * blockDim.x + threadIdx.x) >> 5;
    int lane = threadIdx.x & 31;
    if (w >= NNODE) return;

    float4 tot = make_float4(0.f, 0.f, 0.f, 0.f);
    for (int k = 0; k <= l; k++) {
        const float* h1 = g_h1m[buf][k];
        const int* esrc = g_esrc + (size_t)k * EPK;
        const float* dv = g_dinv + (size_t)k * NNODE;
        int beg = g_rowptr[k * (NNODE + 1) + w];
        int end = g_rowptr[k * (NNODE + 1) + w + 1];
        float di = __ldg(dv + w);
        float4 a0 = make_float4(0.f, 0.f, 0.f, 0.f);
        float4 a1 = make_float4(0.f, 0.f, 0.f, 0.f);
        int e = beg;
        for (; e + 1 < end; e += 2) {
            int s0 = __ldg(esrc + e), s1 = __ldg(esrc + e + 1);
            float c0 = __ldg(dv + s0) * di, c1 = __ldg(dv + s1) * di;
            float4 v0 = *reinterpret_cast<const float4*>(h1 + (size_t)s0 * HID + lane * 4);
            float4 v1 = *reinterpret_cast<const float4*>(h1 + (size_t)s1 * HID + lane * 4);
            a0.x = fmaf(c0, v0.x, a0.x); a0.y = fmaf(c0, v0.y, a0.y);
            a0.z = fmaf(c0, v0.z, a0.z); a0.w = fmaf(c0, v0.w, a0.w);
            a1.x = fmaf(c1, v1.x, a1.x); a1.y = fmaf(c1, v1.y, a1.y);
            a1.z = fmaf(c1, v1.z, a1.z); a1.w = fmaf(c1, v1.w, a1.w);
        }
        if (e < end) {
            int s0 = __ldg(esrc + e);
            float c0 = __ldg(dv + s0) * di;
            float4 v0 = *reinterpret_cast<const float4*>(h1 + (size_t)s0 * HID + lane * 4);
            a0.x = fmaf(c0, v0.x, a0.x); a0.y = fmaf(c0, v0.y, a0.y);
            a0.z = fmaf(c0, v0.z, a0.z); a0.w = fmaf(c0, v0.w, a0.w);
        }
        float sc = di * di;
        float4 hv = *reinterpret_cast<const float4*>(h1 + (size_t)w * HID + lane * 4);
        float4 bv = *reinterpret_cast<const float4*>(conv_b + (size_t)(ci0 + k) * HID + lane * 4);
        float invk = 1.0f / (float)(k + 1);
        tot.x += (a0.x + a1.x + sc * hv.x + bv.x) * invk;
        tot.y += (a0.y + a1.y + sc * hv.y + bv.y) * invk;
        tot.z += (a0.z + a1.z + sc * hv.z + bv.z) * invk;
        tot.w += (a0.w + a1.w + sc * hv.w + bv.w) * invk;
    }

    float4 r = make_float4(fmaxf(tot.x, 0.f), fmaxf(tot.y, 0.f),
                           fmaxf(tot.z, 0.f), fmaxf(tot.w, 0.f));
    uint32_t* oh = g_hbh[l + 1];
    uint32_t* ol = g_hbl[l + 1];
    uint32_t h0, l0, h1b, l1b;
    split_pair(r.x, r.y, h0, l0);
    split_pair(r.z, r.w, h1b, l1b);
    oh[(size_t)w * 64 + lane * 2] = h0;
    oh[(size_t)w * 64 + lane * 2 + 1] = h1b;
    ol[(size_t)w * 64 + lane * 2] = l0;
    ol[(size_t)w * 64 + lane * 2 + 1] = l1b;
    if (write_float)
        *reinterpret_cast<float4*>(g_x5 + (size_t)w * HID + lane * 4) = r;
}

// ---------------- pooling ----------------------------------------------------
__global__ void pool_kernel(const int* __restrict__ batch,
                            const float* __restrict__ h,
                            float* __restrict__ pooled) {
    int g = blockIdx.x;
    int c = threadIdx.x;
    __shared__ int s_lo, s_hi;
    if (c == 0) {
        int lo = 0, hi = NNODE;
        while (lo < hi) { int m = (lo + hi) >> 1; if (batch[m] < g) lo = m + 1; else hi = m; }
        s_lo = lo;
        int lo2 = lo, hi2 = NNODE;
        while (lo2 < hi2) { int m = (lo2 + hi2) >> 1; if (batch[m] < g + 1) lo2 = m + 1; else hi2 = m; }
        s_hi = lo2;
    }
    __syncthreads();
    int lo = s_lo, hi = s_hi;
    float s = 0.f, mx = -3.402823466e38f;
    for (int i = lo; i < hi; i++) {
        float v = h[(size_t)i * HID + c];
        s += v;
        mx = fmaxf(mx, v);
    }
    float cntf = (float)(hi - lo);
    pooled[g * 384 + c] = s;
    pooled[g * 384 + 128 + c] = mx;
    pooled[g * 384 + 256 + c] = s / fmaxf(cntf, 1.f);
}

// ---------------- MLP head ---------------------------------------------------
__global__ void mlp_kernel(const float* __restrict__ pooled,
                           const float* __restrict__ r1W, const float* __restrict__ r1b,
                           const float* __restrict__ r2W, const float* __restrict__ r2b,
                           float* __restrict__ out) {
    int g = blockIdx.x;
    int j = threadIdx.x;  // 192 threads
    __shared__ float sp[384];
    __shared__ float sh[192];
    for (int t = j; t < 384; t += 192) sp[t] = pooled[g * 384 + t];
    __syncthreads();
    float acc = r1b[j];
    const float* wr = r1W + (size_t)j * 384;
#pragma unroll 4
    for (int t = 0; t < 384; t++) acc = fmaf(sp[t], wr[t], acc);
    sh[j] = acc > 0.f ? acc : 0.01f * acc;
    __syncthreads();
    if (j < OUT_DIMS) {
        float a2 = r2b[j];
        const float* w2 = r2W + (size_t)j * 192;
#pragma unroll 4
        for (int t = 0; t < 192; t++) a2 = fmaf(sh[t], w2[t], a2);
        out[g * OUT_DIMS + j] = a2;
    }
}

// ---------------- launch ----------------------------------------------------
extern "C" void kernel_launch(void* const* d_in, const int* in_sizes, int n_in,
                              void* d_out, int out_size) {
    const float* x      = (const float*)d_in[0];
    const int*   kei    = (const int*)d_in[1];
    const int*   batch  = (const int*)d_in[3];
    const float* emb_W  = (const float*)d_in[4];
    const float* emb_b  = (const float*)d_in[5];
    const float* conv_W = (const float*)d_in[6];
    const float* conv_b = (const float*)d_in[7];
    const float* r1_W   = (const float*)d_in[8];
    const float* r1_b   = (const float*)d_in[9];
    const float* r2_W   = (const float*)d_in[10];
    const float* r2_b   = (const float*)d_in[11];
    float* out = (float*)d_out;

    float* pooled;
    float* x5;
    int* cntp;
    uint32_t *xbh, *xbl, *wembh, *wembl, *wconvh, *wconvl;
    cudaGetSymbolAddress((void**)&x5, g_x5);
    cudaGetSymbolAddress((void**)&pooled, g_pooled);
    cudaGetSymbolAddress((void**)&cntp, g_cnt);
    cudaGetSymbolAddress((void**)&xbh, g_xbh);
    cudaGetSymbolAddress((void**)&xbl, g_xbl);
    cudaGetSymbolAddress((void**)&wembh, g_wembh);
    cudaGetSymbolAddress((void**)&wembl, g_wembl);
    cudaGetSymbolAddress((void**)&wconvh, g_wconvh);
    cudaGetSymbolAddress((void**)&wconvl, g_wconvl);

    const int SMEM128 = (128 * 64 * 2 + 64 * 64 * 2) * 4;   // 98304 B
    const int SMEM32  = (128 * 16 * 2 + 64 * 16 * 2) * 4;   // 24576 B
    cudaFuncSetAttribute(gemm_layer, cudaFuncAttributeMaxDynamicSharedMemorySize, SMEM128);
    cudaFuncSetAttribute(gemm_emb, cudaFuncAttributeMaxDynamicSharedMemorySize, SMEM32);

    const bool ov = g_ov.ok;
    cudaStream_t S0 = 0;
    cudaStream_t S1 = ov ? g_ov.s1 : (cudaStream_t)0;

    const int mtiles = (NNODE + 63) / 64;           // 782
    const int agg_grid = (NNODE * 32 + 255) / 256;
    dim3 sg(SCAN_BLOCKS, KCH);

    // ---- fork ----
    if (ov) { cudaEventRecord(g_ov.eFork, S0); cudaStreamWaitEvent(S1, g_ov.eFork, 0); }

    // ---- S1: CSR chain ----
    cudaMemsetAsync(cntp, 0, sizeof(int) * KCH * NNODE, S1);
    count_kernel<<<(NEDGE + 255) / 256, 256, 0, S1>>>(kei);
    scan1_kernel<<<sg, 256, 0, S1>>>();
    scan2_kernel<<<1, 32, 0, S1>>>();
    scan3_kernel<<<sg, 256, 0, S1>>>();
    scatter_kernel<<<(NEDGE + 255) / 256, 256, 0, S1>>>(kei);
    if (ov) cudaEventRecord(g_ov.eCsr, S1);

    // ---- S0: prep + embedding + layer-0 GEMM ----
    prep_pairs<<<(NNODE * 16 + 255) / 256, 256, 0, S0>>>(x, xbh, xbl, NNODE * 16);
    prep_pairs<<<(128 * 16 + 255) / 256, 256, 0, S0>>>(emb_W, wembh, wembl, 128 * 16);
    prep_pairs<<<(15 * 128 * 64 + 255) / 256, 256, 0, S0>>>(conv_W, wconvh, wconvl, 15 * 128 * 64);
    gemm_emb<<<mtiles, 256, SMEM32, S0>>>(emb_b);
    if (ov) cudaEventRecord(g_ov.eEmb, S0);
    gemm_layer<<<mtiles, 256, SMEM128, S0>>>(0, 0, 0, 0);      // layer 0, buf 0

    // ---- S1: OLD_1 (layer 1, y=1; reads hbh[0] <- emb) ----
    if (ov) cudaStreamWaitEvent(S1, g_ov.eEmb, 0);
    gemm_layer<<<dim3(mtiles, 1), 256, SMEM128, S1>>>(1, 1, 1, 1);
    if (ov) cudaEventRecord(g_ov.eOld[1], S1);

    // ---- S0: A_0 ----
    if (ov) cudaStreamWaitEvent(S0, g_ov.eCsr, 0);
    agg_layer<<<agg_grid, 256, 0, S0>>>(0, 0, conv_b, 0, 0);
    if (ov) cudaEventRecord(g_ov.eA[0], S0);

    // layer 1: NEW on S0, then A_1
    gemm_layer<<<mtiles, 256, SMEM128, S0>>>(1, 1, 0, 1);
    if (ov) cudaStreamWaitEvent(S0, g_ov.eOld[1], 0);
    agg_layer<<<agg_grid, 256, 0, S0>>>(1, 1, conv_b, 0, 1);
    if (ov) cudaEventRecord(g_ov.eA[1], S0);

    // ---- S1: OLD_2 (y=1..2; reads hbh[0..1]; h1m buf 0 free after A_0) ----
    if (ov) cudaStreamWaitEvent(S1, g_ov.eA[0], 0);
    gemm_layer<<<dim3(mtiles, 2), 256, SMEM128, S1>>>(2, 3, 1, 0);
    if (ov) cudaEventRecord(g_ov.eOld[2], S1);

    // layer 2
    gemm_layer<<<mtiles, 256, SMEM128, S0>>>(2, 3, 0, 0);
    if (ov) cudaStreamWaitEvent(S0, g_ov.eOld[2], 0);
    agg_layer<<<agg_grid, 256, 0, S0>>>(2, 3, conv_b, 0, 0);
    if (ov) cudaEventRecord(g_ov.eA[2], S0);

    // ---- S1: OLD_3 ----
    if (ov) cudaStreamWaitEvent(S1, g_ov.eA[1], 0);
    gemm_layer<<<dim3(mtiles, 3), 256, SMEM128, S1>>>(3, 6, 1, 1);
    if (ov) cudaEventRecord(g_ov.eOld[3], S1);

    // layer 3
    gemm_layer<<<mtiles, 256, SMEM128, S0>>>(3, 6, 0, 1);
    if (ov) cudaStreamWaitEvent(S0, g_ov.eOld[3], 0);
    agg_layer<<<agg_grid, 256, 0, S0>>>(3, 6, conv_b, 0, 1);
    if (ov) cudaEventRecord(g_ov.eA[3], S0);

    // ---- S1: OLD_4 ----
    if (ov) cudaStreamWaitEvent(S1, g_ov.eA[2], 0);
    gemm_layer<<<dim3(mtiles, 4), 256, SMEM128, S1>>>(4, 10, 1, 0);
    if (ov) cudaEventRecord(g_ov.eOld[4], S1);

    // layer 4
    gemm_layer<<<mtiles, 256, SMEM128, S0>>>(4, 10, 0, 0);
    if (ov) cudaStreamWaitEvent(S0, g_ov.eOld[4], 0);
    agg_layer<<<agg_grid, 256, 0, S0>>>(4, 10, conv_b, 1, 0);

    // ---- tail ----
    pool_kernel<<<NGROUP, HID, 0, S0>>>(batch, x5, pooled);
    mlp_kernel<<<NGROUP, 192, 0, S0>>>(pooled, r1_W, r1_b, r2_W, r2_b, out);
}

// round 17
// speedup vs baseline: 1.0620x; 1.0620x over previous
#include <cuda_runtime.h>
#include <cuda_bf16.h>
#include <cstdint>
#include <cstddef>

#define NNODE 50000
#define IN_DIM 32
#define HID 128
#define OUT_DIMS 10
#define KCH 5
#define EPK 400000
#define NEDGE (KCH * EPK)
#define NGROUP 500
#define SCAN_BLOCKS 25   // ceil(50000/2048)

// ---------------- scratch (device globals; no allocations allowed) ----------
__device__ float g_h1m[KCH][(size_t)NNODE * HID]; // per-k GEMM outputs (layer-local)
__device__ float g_x5[(size_t)NNODE * HID];       // final activations (pool input)
__device__ uint32_t g_hbh[6][(size_t)NNODE * 64]; // x_l bf16-hi (bf16x2 words)
__device__ uint32_t g_hbl[6][(size_t)NNODE * 64]; // x_l bf16-lo
__device__ uint32_t g_xbh[(size_t)NNODE * 16];    // x bf16-hi (K=32)
__device__ uint32_t g_xbl[(size_t)NNODE * 16];
__device__ uint32_t g_wembh[128 * 16];            // emb_W bf16 hi/lo
__device__ uint32_t g_wembl[128 * 16];
__device__ uint32_t g_wconvh[15 * 128 * 64];      // conv_W bf16 hi/lo
__device__ uint32_t g_wconvl[15 * 128 * 64];
__device__ float g_dinv[KCH * NNODE];
__device__ int   g_cnt[KCH * NNODE];
__device__ int   g_rowptr[KCH * (NNODE + 1)];
__device__ int   g_cursor[KCH * NNODE];
__device__ int   g_bsum[KCH * SCAN_BLOCKS];
__device__ int2  g_epack[NEDGE];                  // {src, coef bits} packed
__device__ float g_pooled[NGROUP * 3 * HID];

// ---------------- host-side stream/events (static init, pre-checkpoint) -----
struct OverlapCtx {
    cudaStream_t s1 = nullptr;
    cudaEvent_t eFork = nullptr, eCsr = nullptr;
    bool ok = false;
    OverlapCtx() {
        bool good = cudaStreamCreateWithFlags(&s1, cudaStreamNonBlocking) == cudaSuccess;
        if (good) good = cudaEventCreateWithFlags(&eFork, cudaEventDisableTiming) == cudaSuccess;
        if (good) good = cudaEventCreateWithFlags(&eCsr, cudaEventDisableTiming) == cudaSuccess;
        ok = good;
    }
};
static OverlapCtx g_ov;

// ---------------- bf16 split helpers ----------------------------------------
__device__ __forceinline__ void split_pair(float x, float y, uint32_t& h, uint32_t& l) {
    __nv_bfloat162 hb = __floats2bfloat162_rn(x, y);
    float hx = __bfloat162float(hb.x), hy = __bfloat162float(hb.y);
    __nv_bfloat162 lb = __floats2bfloat162_rn(x - hx, y - hy);
    h = *reinterpret_cast<uint32_t*>(&hb);
    l = *reinterpret_cast<uint32_t*>(&lb);
}

__global__ void prep_pairs(const float* __restrict__ src, uint32_t* __restrict__ dh,
                           uint32_t* __restrict__ dl, int npairs) {
    int i = blockIdx.x * blockDim.x + threadIdx.x;
    if (i >= npairs) return;
    float2 v = *reinterpret_cast<const float2*>(src + (size_t)i * 2);
    uint32_t h, l;
    split_pair(v.x, v.y, h, l);
    dh[i] = h;
    dl[i] = l;
}

// ---------------- CSR build -------------------------------------------------
__global__ void count_kernel(const int* __restrict__ kei) {
    int e = blockIdx.x * blockDim.x + threadIdx.x;
    if (e >= NEDGE) return;
    int chunk = e / EPK;
    int d = kei[NEDGE + e];
    atomicAdd(&g_cnt[chunk * NNODE + d], 1);
}

// scan1 also computes dinv (reads the same counts)
__global__ void scan1_kernel() {
    int ch = blockIdx.y, bx = blockIdx.x, tid = threadIdx.x;
    const int* cnt = g_cnt + ch * NNODE;
    int base = bx * 2048 + tid * 8;
    int tot = 0;
#pragma unroll
    for (int i = 0; i < 8; i++) {
        int idx = base + i;
        if (idx < NNODE) {
            int c = cnt[idx];
            tot += c;
            g_dinv[ch * NNODE + idx] = rsqrtf((float)c + 1.0f);
        }
    }
    __shared__ int s[256];
    s[tid] = tot; __syncthreads();
    for (int off = 128; off > 0; off >>= 1) {
        if (tid < off) s[tid] += s[tid + off];
        __syncthreads();
    }
    if (tid == 0) g_bsum[ch * SCAN_BLOCKS + bx] = s[0];
}

__global__ void scan2_kernel() {
    int c = threadIdx.x;
    if (c >= KCH) return;
    int run = 0;
    for (int b = 0; b < SCAN_BLOCKS; b++) {
        int t = g_bsum[c * SCAN_BLOCKS + b];
        g_bsum[c * SCAN_BLOCKS + b] = run;
        run += t;
    }
    g_rowptr[c * (NNODE + 1) + NNODE] = run;
}

__global__ void scan3_kernel() {
    int ch = blockIdx.y, bx = blockIdx.x, tid = threadIdx.x;
    const int* cnt = g_cnt + ch * NNODE;
    int base = bx * 2048 + tid * 8;
    int v[8]; int tot = 0;
#pragma unroll
    for (int i = 0; i < 8; i++) {
        int idx = base + i;
        v[i] = (idx < NNODE) ? cnt[idx] : 0;
        tot += v[i];
    }
    __shared__ int s[256];
    s[tid] = tot; __syncthreads();
    for (int off = 1; off < 256; off <<= 1) {
        int t = (tid >= off) ? s[tid - off] : 0;
        __syncthreads();
        s[tid] += t;
        __syncthreads();
    }
    int excl = s[tid] - tot + g_bsum[ch * SCAN_BLOCKS + bx];
    int* rowp = g_rowptr + ch * (NNODE + 1);
    int* curs = g_cursor + ch * NNODE;
#pragma unroll
    for (int i = 0; i < 8; i++) {
        int idx = base + i;
        if (idx < NNODE) { rowp[idx] = excl; curs[idx] = excl; }
        excl += v[i];
    }
}

__global__ void scatter_kernel(const int* __restrict__ kei) {
    int e = blockIdx.x * blockDim.x + threadIdx.x;
    if (e >= NEDGE) return;
    int chunk = e / EPK;
    int s = kei[e];
    int d = kei[NEDGE + e];
    int pos = atomicAdd(&g_cursor[chunk * NNODE + d], 1);
    float coef = g_dinv[chunk * NNODE + s] * g_dinv[chunk * NNODE + d];
    g_epack[(size_t)chunk * EPK + pos] = make_int2(s, __float_as_int(coef));
}

// ---------------- split-bf16 mma.sync GEMM core ------------------------------
__device__ __forceinline__ void mma_bf16(float* c, const uint32_t* a,
                                         uint32_t b0, uint32_t b1) {
    asm volatile(
        "mma.sync.aligned.m16n8k16.row.col.f32.bf16.bf16.f32 "
        "{%0,%1,%2,%3}, {%4,%5,%6,%7}, {%8,%9}, {%0,%1,%2,%3};"
        : "+f"(c[0]), "+f"(c[1]), "+f"(c[2]), "+f"(c[3])
        : "r"(a[0]), "r"(a[1]), "r"(a[2]), "r"(a[3]), "r"(b0), "r"(b1));
}

template <int K>
__device__ __forceinline__ void gemm_body(
    const uint32_t* __restrict__ Ah, const uint32_t* __restrict__ Al,
    const uint32_t* __restrict__ Wh, const uint32_t* __restrict__ Wl,
    const float* __restrict__ bias, float* __restrict__ C,
    uint32_t* __restrict__ Ch, uint32_t* __restrict__ Cl, int M, int m0,
    uint32_t* sm) {
    constexpr int RW = K / 2;
    constexpr int NQ = RW / 4;
    constexpr int QM = (NQ >= 8) ? 7 : (NQ - 1);
    constexpr int NKC = K / 16;

    uint32_t* sWh = sm;
    uint32_t* sWl = sWh + 128 * RW;
    uint32_t* sAh = sWl + 128 * RW;
    uint32_t* sAl = sAh + 64 * RW;

    int tid = threadIdx.x;
    int lane = tid & 31, warp = tid >> 5;
    int wm = warp >> 1, wn = warp & 1;

    for (int idx = tid; idx < 128 * NQ; idx += 256) {
        int r = idx / NQ, q = idx % NQ;
        int dq = q ^ (r & QM);
        *reinterpret_cast<uint4*>(sWh + r * RW + dq * 4) =
            *reinterpret_cast<const uint4*>(Wh + (size_t)r * RW + q * 4);
        *reinterpret_cast<uint4*>(sWl + r * RW + dq * 4) =
            *reinterpret_cast<const uint4*>(Wl + (size_t)r * RW + q * 4);
    }
    for (int idx = tid; idx < 64 * NQ; idx += 256) {
        int r = idx / NQ, q = idx % NQ;
        int row = m0 + r; if (row >= M) row = M - 1;
        int dq = q ^ (r & QM);
        *reinterpret_cast<uint4*>(sAh + r * RW + dq * 4) =
            *reinterpret_cast<const uint4*>(Ah + (size_t)row * RW + q * 4);
        *reinterpret_cast<uint4*>(sAl + r * RW + dq * 4) =
            *reinterpret_cast<const uint4*>(Al + (size_t)row * RW + q * 4);
    }
    __syncthreads();

    float c[8][4];
#pragma unroll
    for (int i = 0; i < 8; i++)
#pragma unroll
        for (int j = 0; j < 4; j++) c[i][j] = 0.f;

    int g = lane >> 2, t = lane & 3;

#define LDW(base, r, w) (base)[(r) * RW + (((((w) >> 2) ^ ((r) & QM))) << 2) + ((w) & 3)]

#pragma unroll
    for (int kc = 0; kc < NKC; kc++) {
        int w0 = kc * 8 + t;
        int w1 = kc * 8 + 4 + t;
        int ra = wm * 16 + g;
        uint32_t ah[4], al[4];
        ah[0] = LDW(sAh, ra, w0);     al[0] = LDW(sAl, ra, w0);
        ah[1] = LDW(sAh, ra + 8, w0); al[1] = LDW(sAl, ra + 8, w0);
        ah[2] = LDW(sAh, ra, w1);     al[2] = LDW(sAl, ra, w1);
        ah[3] = LDW(sAh, ra + 8, w1); al[3] = LDW(sAl, ra + 8, w1);
#pragma unroll
        for (int nt = 0; nt < 8; nt++) {
            int n = wn * 64 + nt * 8 + g;
            uint32_t bh0 = LDW(sWh, n, w0), bh1 = LDW(sWh, n, w1);
            uint32_t bl0 = LDW(sWl, n, w0), bl1 = LDW(sWl, n, w1);
            mma_bf16(c[nt], ah, bh0, bh1);
            mma_bf16(c[nt], al, bh0, bh1);
            mma_bf16(c[nt], ah, bl0, bl1);
        }
    }
#undef LDW

    int r0 = m0 + wm * 16 + g;
    int r1 = r0 + 8;
#pragma unroll
    for (int nt = 0; nt < 8; nt++) {
        int col = wn * 64 + nt * 8 + t * 2;
        float bx = 0.f, by = 0.f;
        if (bias) { bx = bias[col]; by = bias[col + 1]; }
        if (r0 < M) {
            float2 o = make_float2(c[nt][0] + bx, c[nt][1] + by);
            if (C) *reinterpret_cast<float2*>(C + (size_t)r0 * HID + col) = o;
            if (Ch) {
                uint32_t h, l;
                split_pair(o.x, o.y, h, l);
                Ch[(size_t)r0 * 64 + (col >> 1)] = h;
                Cl[(size_t)r0 * 64 + (col >> 1)] = l;
            }
        }
        if (r1 < M) {
            float2 o = make_float2(c[nt][2] + bx, c[nt][3] + by);
            if (C) *reinterpret_cast<float2*>(C + (size_t)r1 * HID + col) = o;
            if (Ch) {
                uint32_t h, l;
                split_pair(o.x, o.y, h, l);
                Ch[(size_t)r1 * 64 + (col >> 1)] = h;
                Cl[(size_t)r1 * 64 + (col >> 1)] = l;
            }
        }
    }
}

// embedding GEMM (K=32): bf16 output only
__global__ __launch_bounds__(256) void gemm_emb(const float* __restrict__ emb_b) {
    extern __shared__ uint32_t sm[];
    gemm_body<IN_DIM>(g_xbh, g_xbl, g_wembh, g_wembl, emb_b,
                      nullptr, g_hbh[0], g_hbl[0], NNODE, blockIdx.x * 64, sm);
}

// batched per-layer conv GEMMs: blockIdx.y = k-1; A = x_l[l-y], C = h1m[y]
__global__ __launch_bounds__(256) void gemm_layer(int l, int ci0) {
    extern __shared__ uint32_t sm[];
    int y = blockIdx.y;
    gemm_body<HID>(g_hbh[l - y], g_hbl[l - y],
                   g_wconvh + (size_t)(ci0 + y) * 128 * 64,
                   g_wconvl + (size_t)(ci0 + y) * 128 * 64,
                   nullptr, g_h1m[y], nullptr, nullptr, NNODE, blockIdx.x * 64, sm);
}

// ---------------- fused per-layer GCN aggregation ----------------------------
__global__ __launch_bounds__(256) void agg_layer(
    int l, int ci0, const float* __restrict__ conv_b, int write_float) {
    int w = (blockIdx.x * blockDim.x + threadIdx.x) >> 5;
    int lane = threadIdx.x & 31;
    if (w >= NNODE) return;

    float4 tot = make_float4(0.f, 0.f, 0.f, 0.f);
    for (int k = 0; k <= l; k++) {
        const float* h1 = g_h1m[k];
        const int2* ep = g_epack + (size_t)k * EPK;
        int beg = g_rowptr[k * (NNODE + 1) + w];
        int end = g_rowptr[k * (NNODE + 1) + w + 1];
        float4 a0 = make_float4(0.f, 0.f, 0.f, 0.f);
        float4 a1 = make_float4(0.f, 0.f, 0.f, 0.f);
        int e = beg;
        for (; e + 1 < end; e += 2) {
            int2 p0 = __ldg(ep + e), p1 = __ldg(ep + e + 1);
            float c0 = __int_as_float(p0.y), c1 = __int_as_float(p1.y);
            float4 v0 = *reinterpret_cast<const float4*>(h1 + (size_t)p0.x * HID + lane * 4);
            float4 v1 = *reinterpret_cast<const float4*>(h1 + (size_t)p1.x * HID + lane * 4);
            a0.x = fmaf(c0, v0.x, a0.x); a0.y = fmaf(c0, v0.y, a0.y);
            a0.z = fmaf(c0, v0.z, a0.z); a0.w = fmaf(c0, v0.w, a0.w);
            a1.x = fmaf(c1, v1.x, a1.x); a1.y = fmaf(c1, v1.y, a1.y);
            a1.z = fmaf(c1, v1.z, a1.z); a1.w = fmaf(c1, v1.w, a1.w);
        }
        if (e < end) {
            int2 p0 = __ldg(ep + e);
            float c0 = __int_as_float(p0.y);
            float4 v0 = *reinterpret_cast<const float4*>(h1 + (size_t)p0.x * HID + lane * 4);
            a0.x = fmaf(c0, v0.x, a0.x); a0.y = fmaf(c0, v0.y, a0.y);
            a0.z = fmaf(c0, v0.z, a0.z); a0.w = fmaf(c0, v0.w, a0.w);
        }
        float di = g_dinv[k * NNODE + w];
        float sc = di * di;
        float4 hv = *reinterpret_cast<const float4*>(h1 + (size_t)w * HID + lane * 4);
        float4 bv = *reinterpret_cast<const float4*>(conv_b + (size_t)(ci0 + k) * HID + lane * 4);
        float invk = 1.0f / (float)(k + 1);
        tot.x += (a0.x + a1.x + sc * hv.x + bv.x) * invk;
        tot.y += (a0.y + a1.y + sc * hv.y + bv.y) * invk;
        tot.z += (a0.z + a1.z + sc * hv.z + bv.z) * invk;
        tot.w += (a0.w + a1.w + sc * hv.w + bv.w) * invk;
    }

    float4 r = make_float4(fmaxf(tot.x, 0.f), fmaxf(tot.y, 0.f),
                           fmaxf(tot.z, 0.f), fmaxf(tot.w, 0.f));
    uint32_t* oh = g_hbh[l + 1];
    uint32_t* ol = g_hbl[l + 1];
    uint32_t h0, l0, h1b, l1b;
    split_pair(r.x, r.y, h0, l0);
    split_pair(r.z, r.w, h1b, l1b);
    oh[(size_t)w * 64 + lane * 2] = h0;
    oh[(size_t)w * 64 + lane * 2 + 1] = h1b;
    ol[(size_t)w * 64 + lane * 2] = l0;
    ol[(size_t)w * 64 + lane * 2 + 1] = l1b;
    if (write_float)
        *reinterpret_cast<float4*>(g_x5 + (size_t)w * HID + lane * 4) = r;
}

// ---------------- pooling ----------------------------------------------------
__global__ void pool_kernel(const int* __restrict__ batch,
                            const float* __restrict__ h,
                            float* __restrict__ pooled) {
    int g = blockIdx.x;
    int c = threadIdx.x;
    __shared__ int s_lo, s_hi;
    if (c == 0) {
        int lo = 0, hi = NNODE;
        while (lo < hi) { int m = (lo + hi) >> 1; if (batch[m] < g) lo = m + 1; else hi = m; }
        s_lo = lo;
        int lo2 = lo, hi2 = NNODE;
        while (lo2 < hi2) { int m = (lo2 + hi2) >> 1; if (batch[m] < g + 1) lo2 = m + 1; else hi2 = m; }
        s_hi = lo2;
    }
    __syncthreads();
    int lo = s_lo, hi = s_hi;
    float s = 0.f, mx = -3.402823466e38f;
    for (int i = lo; i < hi; i++) {
        float v = h[(size_t)i * HID + c];
        s += v;
        mx = fmaxf(mx, v);
    }
    float cntf = (float)(hi - lo);
    pooled[g * 384 + c] = s;
    pooled[g * 384 + 128 + c] = mx;
    pooled[g * 384 + 256 + c] = s / fmaxf(cntf, 1.f);
}

// ---------------- MLP head ---------------------------------------------------
__global__ void mlp_kernel(const float* __restrict__ pooled,
                           const float* __restrict__ r1W, const float* __restrict__ r1b,
                           const float* __restrict__ r2W, const float* __restrict__ r2b,
                           float* __restrict__ out) {
    int g = blockIdx.x;
    int j = threadIdx.x;  // 192 threads
    __shared__ float sp[384];
    __shared__ float sh[192];
    for (int t = j; t < 384; t += 192) sp[t] = pooled[g * 384 + t];
    __syncthreads();
    float acc = r1b[j];
    const float* wr = r1W + (size_t)j * 384;
#pragma unroll 4
    for (int t = 0; t < 384; t++) acc = fmaf(sp[t], wr[t], acc);
    sh[j] = acc > 0.f ? acc : 0.01f * acc;
    __syncthreads();
    if (j < OUT_DIMS) {
        float a2 = r2b[j];
        const float* w2 = r2W + (size_t)j * 192;
#pragma unroll 4
        for (int t = 0; t < 192; t++) a2 = fmaf(sh[t], w2[t], a2);
        out[g * OUT_DIMS + j] = a2;
    }
}

// ---------------- launch ----------------------------------------------------
extern "C" void kernel_launch(void* const* d_in, const int* in_sizes, int n_in,
                              void* d_out, int out_size) {
    const float* x      = (const float*)d_in[0];
    const int*   kei    = (const int*)d_in[1];
    const int*   batch  = (const int*)d_in[3];
    const float* emb_W  = (const float*)d_in[4];
    const float* emb_b  = (const float*)d_in[5];
    const float* conv_W = (const float*)d_in[6];
    const float* conv_b = (const float*)d_in[7];
    const float* r1_W   = (const float*)d_in[8];
    const float* r1_b   = (const float*)d_in[9];
    const float* r2_W   = (const float*)d_in[10];
    const float* r2_b   = (const float*)d_in[11];
    float* out = (float*)d_out;

    float *x5, *pooled;
    int* cntp;
    uint32_t *xbh, *xbl, *wembh, *wembl, *wconvh, *wconvl;
    cudaGetSymbolAddress((void**)&x5, g_x5);
    cudaGetSymbolAddress((void**)&pooled, g_pooled);
    cudaGetSymbolAddress((void**)&cntp, g_cnt);
    cudaGetSymbolAddress((void**)&xbh, g_xbh);
    cudaGetSymbolAddress((void**)&xbl, g_xbl);
    cudaGetSymbolAddress((void**)&wembh, g_wembh);
    cudaGetSymbolAddress((void**)&wembl, g_wembl);
    cudaGetSymbolAddress((void**)&wconvh, g_wconvh);
    cudaGetSymbolAddress((void**)&wconvl, g_wconvl);

    const int SMEM128 = (128 * 64 * 2 + 64 * 64 * 2) * 4;   // 98304 B
    const int SMEM32  = (128 * 16 * 2 + 64 * 16 * 2) * 4;   // 24576 B
    cudaFuncSetAttribute(gemm_layer, cudaFuncAttributeMaxDynamicSharedMemorySize, SMEM128);
    cudaFuncSetAttribute(gemm_emb, cudaFuncAttributeMaxDynamicSharedMemorySize, SMEM32);

    const bool ov = g_ov.ok;
    cudaStream_t S0 = 0;
    cudaStream_t S1 = ov ? g_ov.s1 : (cudaStream_t)0;

    const int mtiles = (NNODE + 63) / 64;           // 782
    const int agg_grid = (NNODE * 32 + 255) / 256;
    dim3 sg(SCAN_BLOCKS, KCH);

    // ---- fork: CSR chain on S1 ----
    if (ov) { cudaEventRecord(g_ov.eFork, S0); cudaStreamWaitEvent(S1, g_ov.eFork, 0); }
    cudaMemsetAsync(cntp, 0, sizeof(int) * KCH * NNODE, S1);
    count_kernel<<<(NEDGE + 255) / 256, 256, 0, S1>>>(kei);
    scan1_kernel<<<sg, 256, 0, S1>>>();
    scan2_kernel<<<1, 32, 0, S1>>>();
    scan3_kernel<<<sg, 256, 0, S1>>>();
    scatter_kernel<<<(NEDGE + 255) / 256, 256, 0, S1>>>(kei);
    if (ov) cudaEventRecord(g_ov.eCsr, S1);

    // ---- S0 meanwhile: prep + embedding + layer-0 GEMM ----
    prep_pairs<<<(NNODE * 16 + 255) / 256, 256, 0, S0>>>(x, xbh, xbl, NNODE * 16);
    prep_pairs<<<(128 * 16 + 255) / 256, 256, 0, S0>>>(emb_W, wembh, wembl, 128 * 16);
    prep_pairs<<<(15 * 128 * 64 + 255) / 256, 256, 0, S0>>>(conv_W, wconvh, wconvl, 15 * 128 * 64);
    gemm_emb<<<mtiles, 256, SMEM32, S0>>>(emb_b);
    gemm_layer<<<mtiles, 256, SMEM128, S0>>>(0, 0);

    // ---- join: agg needs CSR ----
    if (ov) cudaStreamWaitEvent(S0, g_ov.eCsr, 0);
    agg_layer<<<agg_grid, 256, 0, S0>>>(0, 0, conv_b, 0);

    // ---- remaining layers fully sequential on S0 ----
    for (int l = 1; l < 5; l++) {
        int ci0 = l * (l + 1) / 2;
        dim3 gg(mtiles, l + 1);
        gemm_layer<<<gg, 256, SMEM128, S0>>>(l, ci0);
        agg_layer<<<agg_grid, 256, 0, S0>>>(l, ci0, conv_b, (l == 4) ? 1 : 0);
    }

    pool_kernel<<<NGROUP, HID, 0, S0>>>(batch, x5, pooled);
    mlp_kernel<<<NGROUP, 192, 0, S0>>>(pooled, r1_W, r1_b, r2_W, r2_b, out);
}